// round 14
// baseline (speedup 1.0000x reference)
#include <cuda_runtime.h>
#include <cuda_bf16.h>
#include <math.h>

// Problem shapes (fixed for this dataset)
#define KDIM 32
#define DDIM 32
#define N_I 5000
#define N_J 5000
#define M_I 2500
#define M_J 2500
#define N_EDGES 200000
#define EPSV 1e-6f
#define C0 (32.0f * EPSV * EPSV)

#define TPB 256
#define GRID 296                      // 2 blocks/SM x 148 SMs; ALL resident (barrier-safe)
#define BT 128                        // pair tile edge
#define NTI ((M_I + BT - 1) / BT)     // 20
#define NTJ ((M_J + BT - 1) / BT)     // 20
#define NPAIR (NTI * NTJ)             // 400
#define EDGE_PER_BLK 2048
#define NEDGE_BLKS ((N_EDGES + EDGE_PER_BLK - 1) / EDGE_PER_BLK)  // 98
#define NITEMS (NPAIR + NEDGE_BLKS)                               // 498

// ---------------- scratch (static device globals; zero-initialized) ----------
// INVARIANT: g_T, g_s, g_mat, g_links, g_done, g_bar are zero at launch entry.
// They start zero (module load) and the final block re-zeroes them each call.
__device__ float g_T[KDIM * KDIM];       // T[a][b] = sum_m Z[a,m] Z[b,m] G[m,b]
__device__ float g_s[KDIM];              // s[b]
__device__ float g_Xi[N_I * DDIM];       // latent rows (128B each)
__device__ float g_qi[N_I];              // ||x||^2 + 2 eps sum(x)
__device__ float g_Xj[N_J * DDIM];
__device__ float g_qj[N_J];              // ||x||^2 - 2 eps sum(x)
__device__ double g_mat;
__device__ double g_links;
__device__ unsigned int g_done;
__device__ int g_bar[4];

// ---------------- helpers ------------------------------------------------------
__device__ __forceinline__ int ld_acq(const int* p) {
    int v;
    asm volatile("ld.acquire.gpu.u32 %0, [%1];" : "=r"(v) : "l"(p));
    return v;
}

// device-wide barrier: grid is exactly 2 blocks/SM (launch_bounds enforced) -> resident
__device__ __forceinline__ void grid_bar(int slot) {
    __syncthreads();
    if (threadIdx.x == 0) {
        __threadfence();
        atomicAdd(&g_bar[slot], 1);
        while (ld_acq(&g_bar[slot]) < (int)gridDim.x) { }
    }
    __syncthreads();
}

__device__ __forceinline__ float block_reduce(float v, float* red) {
#pragma unroll
    for (int o = 16; o; o >>= 1) v += __shfl_down_sync(0xffffffffu, v, o);
    int t = threadIdx.x;
    if ((t & 31) == 0) red[t >> 5] = v;
    __syncthreads();
    float s = 0.f;
    if (t == 0) {
#pragma unroll
        for (int i = 0; i < TPB / 32; i++) s += red[i];
    }
    __syncthreads();   // red reusable afterwards
    return s;          // valid on t==0 only
}

// ---------------- fused kernel: stats -> latent -> pair/edges ------------------
__global__ void __launch_bounds__(TPB, 2) k_fused(
    const float* __restrict__ beta, const float* __restrict__ gamma,
    const float* __restrict__ A,
    const float* __restrict__ Z_i, const float* __restrict__ Z_j,
    const float* __restrict__ Gate,
    const int* __restrict__ si, const int* __restrict__ sj,
    const int* __restrict__ spi, const int* __restrict__ spj,
    float* __restrict__ out)
{
    __shared__ float s_As[KDIM][BT + 4];   // phase1: sT(32x33); phase2: az(32x32); phase3: A tile
    __shared__ float s_Bs[KDIM][BT + 4];   // phase1: ss(32);    phase3: B tile
    __shared__ float s_qa[BT], s_ba[BT], s_qb[BT], s_gb[BT];
    __shared__ float s_red[TPB / 32];

    const int tid = threadIdx.x;
    const int bid = blockIdx.x;
    const int lane = tid & 31;

    // ===== Phase 1: gate statistics (smem-reduced; inline warp softmax) =====
    {
        float* sT = &s_As[0][0];           // [a*(KDIM+1)+b] layout, 33-stride (bank-rotated)
        float* ss = &s_Bs[0][0];
        for (int e = tid; e < KDIM * (KDIM + 1); e += TPB) sT[e] = 0.f;
        if (tid < KDIM) ss[tid] = 0.f;
        __syncthreads();

        const int gwarp = (bid * TPB + tid) >> 5;
        const int nwarps = (GRID * TPB) >> 5;   // 2368 warps -> ~2.1 samples each

        float sacc = 0.f;
        float tacc[KDIM];
#pragma unroll
        for (int a = 0; a < KDIM; a++) tacc[a] = 0.f;

        for (int m = gwarp; m < M_I + M_J; m += nwarps) {
            int idx; const float* Zsrc; int n;
            if (m < M_I) { idx = si[m]; Zsrc = Z_i; n = N_I; }
            else         { idx = sj[m - M_I]; Zsrc = Z_j; n = N_J; }
            float gt = Gate[idx * KDIM + lane];  // issue early
            float zv = Zsrc[lane * n + idx];
            float mx = zv;
#pragma unroll
            for (int o = 16; o; o >>= 1) mx = fmaxf(mx, __shfl_xor_sync(0xffffffffu, mx, o));
            float e = __expf(zv - mx);
            float es = e;
#pragma unroll
            for (int o = 16; o; o >>= 1) es += __shfl_xor_sync(0xffffffffu, es, o);
            float z = e / es;

            float g = 1.f / (1.f + __expf(-gt));   // faithful: j-side indexes Gate w/o offset
            float w = z * g;
            sacc += w;
#pragma unroll
            for (int a = 0; a < KDIM; a++) {
                float za = __shfl_sync(0xffffffffu, z, a);
                tacc[a] = fmaf(za, w, tacc[a]);
            }
        }

        atomicAdd(&ss[lane], sacc);
#pragma unroll
        for (int a = 0; a < KDIM; a++) atomicAdd(&sT[a * (KDIM + 1) + lane], tacc[a]);
        __syncthreads();

        for (int e = tid; e < KDIM * KDIM; e += TPB)
            atomicAdd(&g_T[e], sT[(e >> 5) * (KDIM + 1) + (e & 31)]);
        if (tid < KDIM) atomicAdd(&g_s[tid], ss[tid]);
    }
    grid_bar(0);

    // ===== Phase 2: AZC (per block, redundant) + per-node latent rows =====
    {
        float (*az)[KDIM] = reinterpret_cast<float (*)[KDIM]>(&s_As[0][0]);
        for (int e = tid; e < DDIM * KDIM; e += TPB) {
            int dd = e >> 5, b = e & 31;
            float acc = 0.f;
#pragma unroll
            for (int a = 0; a < KDIM; a++) acc = fmaf(A[dd * KDIM + a], g_T[a * KDIM + b], acc);
            az[dd][b] = acc / g_s[b];
        }
        __syncthreads();

        for (int c = bid * TPB + tid; c < N_I + N_J; c += GRID * TPB) {
            const float* Zsrc; float* X; float* q; int n, cc, side;
            if (c < N_I) { Zsrc = Z_i; X = g_Xi; q = g_qi; n = N_I; cc = c; side = 0; }
            else         { Zsrc = Z_j; X = g_Xj; q = g_qj; n = N_J; cc = c - N_I; side = 1; }

            float v[KDIM];
            float mx = -1e30f;
#pragma unroll
            for (int a = 0; a < KDIM; a++) { v[a] = Zsrc[a * n + cc]; mx = fmaxf(mx, v[a]); }
            float sum = 0.f;
#pragma unroll
            for (int a = 0; a < KDIM; a++) { v[a] = __expf(v[a] - mx); sum += v[a]; }
            float inv = 1.f / sum;

            float x[DDIM];
#pragma unroll
            for (int dd = 0; dd < DDIM; dd++) x[dd] = 0.f;
#pragma unroll
            for (int a = 0; a < KDIM; a++) {
                float z = v[a] * inv;
#pragma unroll
                for (int dd = 0; dd < DDIM; dd++) x[dd] = fmaf(az[dd][a], z, x[dd]);
            }
            float s2 = 0.f, s1 = 0.f;
            float4* o4 = (float4*)&X[cc * DDIM];
#pragma unroll
            for (int w = 0; w < DDIM / 4; w++) {
                float4 v4 = make_float4(x[4 * w], x[4 * w + 1], x[4 * w + 2], x[4 * w + 3]);
                s2 = fmaf(v4.x, v4.x, fmaf(v4.y, v4.y, fmaf(v4.z, v4.z, fmaf(v4.w, v4.w, s2))));
                s1 += v4.x + v4.y + v4.z + v4.w;
                o4[w] = v4;
            }
            q[cc] = side == 0 ? (s2 + 2.f * EPSV * s1) : (s2 - 2.f * EPSV * s1);
        }
    }
    grid_bar(1);

    // ===== Phase 3: pair tiles + edge chunks (item loop) =====
    for (int item = bid; item < NITEMS; item += GRID) {
        __syncthreads();   // protect smem reuse across item iterations
        if (item < NPAIR) {
            // ---- dense pairwise exp-distance tile (BT x BT) ----
            int ti = item / NTJ, tj = item - ti * NTJ;
            int i0 = ti * BT, j0 = tj * BT;

            for (int e = tid; e < BT * KDIM; e += TPB) {
                int r = e >> 5, kk = e & 31;       // lanes sweep kk -> coalesced row reads
                int rg = i0 + r;
                float v = 0.f;
                if (rg < M_I) v = g_Xi[si[rg] * DDIM + kk];
                s_As[kk][r] = v;
                rg = j0 + r;
                v = 0.f;
                if (rg < M_J) v = g_Xj[sj[rg] * DDIM + kk];
                s_Bs[kk][r] = v;
            }
            if (tid < BT) {
                int rg = i0 + tid;
                if (rg < M_I) { int idx = si[rg]; s_qa[tid] = g_qi[idx]; s_ba[tid] = beta[idx]; }
                else          { s_qa[tid] = 1e30f; s_ba[tid] = 0.f; }
            } else {
                int p = tid - BT;
                int rg = j0 + p;
                if (rg < M_J) { int idx = sj[rg]; s_qb[p] = g_qj[idx]; s_gb[p] = gamma[idx]; }
                else          { s_qb[p] = 1e30f; s_gb[p] = 0.f; }
            }
            __syncthreads();

            const int tx = tid & 15, ty = tid >> 4;
            const int r0 = ty * 8, c0 = tx * 8;

            unsigned long long acc[8][4];
#pragma unroll
            for (int r = 0; r < 8; r++)
#pragma unroll
                for (int c = 0; c < 4; c++) acc[r][c] = 0ULL;

#pragma unroll
            for (int kk = 0; kk < KDIM; kk++) {
                float4 a0 = *(const float4*)&s_As[kk][r0];
                float4 a1 = *(const float4*)&s_As[kk][r0 + 4];
                ulonglong2 b0 = *(const ulonglong2*)&s_Bs[kk][c0];
                ulonglong2 b1 = *(const ulonglong2*)&s_Bs[kk][c0 + 4];
                float av[8] = {a0.x, a0.y, a0.z, a0.w, a1.x, a1.y, a1.z, a1.w};
                unsigned long long bp[4] = {b0.x, b0.y, b1.x, b1.y};
#pragma unroll
                for (int r = 0; r < 8; r++) {
                    unsigned long long ad;
                    asm("mov.b64 %0, {%1, %1};" : "=l"(ad) : "f"(av[r]));
#pragma unroll
                    for (int c = 0; c < 4; c++) {
                        asm("fma.rn.f32x2 %0, %1, %2, %0;"
                            : "+l"(acc[r][c]) : "l"(ad), "l"(bp[c]));
                    }
                }
            }

            float sum = 0.f;
#pragma unroll
            for (int r = 0; r < 8; r++) {
                float qa = s_qa[r0 + r];
                float ba = s_ba[r0 + r];
#pragma unroll
                for (int c = 0; c < 4; c++) {
                    float dlo, dhi;
                    asm("mov.b64 {%0, %1}, %2;" : "=f"(dlo), "=f"(dhi) : "l"(acc[r][c]));
                    int cl = c0 + 2 * c;
                    float d2a = qa + s_qb[cl] - 2.f * dlo + C0;
                    float d2b = qa + s_qb[cl + 1] - 2.f * dhi + C0;
                    d2a = fmaxf(d2a, 0.f);
                    d2b = fmaxf(d2b, 0.f);
                    sum += __expf(ba + s_gb[cl] - sqrtf(d2a));
                    sum += __expf(ba + s_gb[cl + 1] - sqrtf(d2b));
                }
            }
            float bs = block_reduce(sum, s_red);
            if (tid == 0) atomicAdd(&g_mat, (double)bs);
        } else {
            // ---- sparse edge chunk ----
            int base = (item - NPAIR) * EDGE_PER_BLK;
            float sum = 0.f;
#pragma unroll
            for (int l = 0; l < EDGE_PER_BLK / TPB; l++) {
                int e = base + l * TPB + tid;
                if (e < N_EDGES) {
                    int ii = spi[e];
                    int jj = spj[e];
                    const float4* xa = (const float4*)&g_Xi[ii * DDIM];
                    const float4* xb = (const float4*)&g_Xj[jj * DDIM];
                    float dot = 0.f;
#pragma unroll
                    for (int w = 0; w < DDIM / 4; w++) {
                        float4 a = xa[w], b = xb[w];
                        dot = fmaf(a.x, b.x, dot);
                        dot = fmaf(a.y, b.y, dot);
                        dot = fmaf(a.z, b.z, dot);
                        dot = fmaf(a.w, b.w, dot);
                    }
                    float d2 = g_qi[ii] + g_qj[jj] - 2.f * dot + C0;
                    d2 = fmaxf(d2, 0.f);
                    sum += beta[ii] + gamma[jj] - sqrtf(d2);
                }
            }
            float bs = block_reduce(sum, s_red);
            if (tid == 0) atomicAdd(&g_links, (double)bs);
        }
    }

    // ---- last-block-done: final scalar + reset ALL state for next replay ----
    __syncthreads();
    __threadfence();
    __shared__ unsigned int s_last;
    if (tid == 0) s_last = atomicAdd(&g_done, 1u);
    __syncthreads();
    if (s_last == GRID - 1) {
        if (tid == 0) {
            double m = atomicAdd(&g_mat, 0.0);      // read after fence chain
            double l = atomicAdd(&g_links, 0.0);
            out[0] = (float)(l - m);
            g_mat = 0.0;
            g_links = 0.0;
            g_done = 0u;
            g_s[0] = 0.f;
            g_bar[0] = 0; g_bar[1] = 0; g_bar[2] = 0; g_bar[3] = 0;
        }
        for (int e = tid; e < KDIM * KDIM; e += TPB) g_T[e] = 0.f;
        if (tid > 0 && tid < KDIM) g_s[tid] = 0.f;
    }
}

// ---------------- launcher -----------------------------------------------------
extern "C" void kernel_launch(void* const* d_in, const int* in_sizes, int n_in,
                              void* d_out, int out_size) {
    const float* beta  = (const float*)d_in[0];
    const float* gamma = (const float*)d_in[1];
    const float* A     = (const float*)d_in[2];
    const float* Z_i   = (const float*)d_in[3];
    const float* Z_j   = (const float*)d_in[4];
    const float* Gate  = (const float*)d_in[5];
    const int* si      = (const int*)d_in[6];
    const int* sj      = (const int*)d_in[7];
    const int* spi     = (const int*)d_in[8];
    const int* spj     = (const int*)d_in[9];
    float* out = (float*)d_out;

    k_fused<<<GRID, TPB>>>(beta, gamma, A, Z_i, Z_j, Gate, si, sj, spi, spj, out);
}

// round 17
// speedup vs baseline: 1.0630x; 1.0630x over previous
#include <cuda_runtime.h>
#include <cuda_bf16.h>
#include <math.h>

// Problem shapes (fixed for this dataset)
#define KDIM 32
#define DDIM 32
#define N_I 5000
#define N_J 5000
#define M_I 2500
#define M_J 2500
#define N_EDGES 200000
#define EPSV 1e-6f
#define C0 (32.0f * EPSV * EPSV)

#define TPB 256
#define KA_GRID 296                   // 2 blocks/SM x 148 SMs; resident (barrier-safe)
#define BT 128                        // pair tile edge
#define NTI ((M_I + BT - 1) / BT)     // 20
#define NTJ ((M_J + BT - 1) / BT)     // 20
#define NPAIR (NTI * NTJ)             // 400
#define EDGE_PER_BLK 2048
#define NEDGE_BLKS ((N_EDGES + EDGE_PER_BLK - 1) / EDGE_PER_BLK)  // 98
#define NITEMS (NPAIR + NEDGE_BLKS)                               // 498
#define KB_GRID 296

// ---------------- scratch (static device globals; zero-initialized) ----------
// INVARIANT: g_T, g_s, g_mat, g_links, g_done, g_bar are zero at launch entry.
// They start zero (module load) and KB's final block re-zeroes them each call.
__device__ float g_T[KDIM * KDIM];       // T[a][b] = sum_m Z[a,m] Z[b,m] G[m,b]
__device__ float g_s[KDIM];              // s[b]
__device__ float g_Xi[N_I * DDIM];       // latent rows (128B each)
__device__ float g_qi[N_I];              // ||x||^2 + 2 eps sum(x)
__device__ float g_Xj[N_J * DDIM];
__device__ float g_qj[N_J];              // ||x||^2 - 2 eps sum(x)
__device__ double g_mat;
__device__ double g_links;
__device__ unsigned int g_done;
__device__ int g_bar[2];

// ---------------- helpers ------------------------------------------------------
__device__ __forceinline__ int ld_acq(const int* p) {
    int v;
    asm volatile("ld.acquire.gpu.u32 %0, [%1];" : "=r"(v) : "l"(p));
    return v;
}

__device__ __forceinline__ float fsqrt_fast(float x) {
    float r;
    asm("sqrt.approx.f32 %0, %1;" : "=f"(r) : "f"(x));
    return r;
}

// device-wide barrier: grid == 2 blocks/SM (launch_bounds enforced) -> resident
__device__ __forceinline__ void grid_bar(int slot) {
    __syncthreads();
    if (threadIdx.x == 0) {
        __threadfence();
        atomicAdd(&g_bar[slot], 1);
        while (ld_acq(&g_bar[slot]) < (int)gridDim.x) { }
    }
    __syncthreads();
}

__device__ __forceinline__ float block_reduce(float v, float* red) {
#pragma unroll
    for (int o = 16; o; o >>= 1) v += __shfl_down_sync(0xffffffffu, v, o);
    int t = threadIdx.x;
    if ((t & 31) == 0) red[t >> 5] = v;
    __syncthreads();
    float s = 0.f;
    if (t == 0) {
#pragma unroll
        for (int i = 0; i < TPB / 32; i++) s += red[i];
    }
    __syncthreads();   // red reusable afterwards
    return s;          // valid on t==0 only
}

// ---------------- KA: gate statistics -> (grid bar) -> latent rows -------------
__global__ void __launch_bounds__(TPB, 2) kA_stats_latent(
    const float* __restrict__ A,
    const float* __restrict__ Z_i, const float* __restrict__ Z_j,
    const float* __restrict__ Gate,
    const int* __restrict__ si, const int* __restrict__ sj)
{
    __shared__ float s_sT[KDIM][KDIM + 1];   // phase1 accum; phase2 az reuses [32][32]
    __shared__ float s_ss[KDIM];

    const int tid = threadIdx.x;
    const int bid = blockIdx.x;
    const int lane = tid & 31;

    // ===== Phase 1: gate statistics (smem-reduced; inline warp softmax) =====
    {
        for (int e = tid; e < KDIM * (KDIM + 1); e += TPB) (&s_sT[0][0])[e] = 0.f;
        if (tid < KDIM) s_ss[tid] = 0.f;
        __syncthreads();

        const int gwarp = (bid * TPB + tid) >> 5;
        const int nwarps = (KA_GRID * TPB) >> 5;   // 2368 warps -> ~2.1 samples each

        float sacc = 0.f;
        float tacc[KDIM];
#pragma unroll
        for (int a = 0; a < KDIM; a++) tacc[a] = 0.f;

        for (int m = gwarp; m < M_I + M_J; m += nwarps) {
            int idx; const float* Zsrc; int n;
            if (m < M_I) { idx = si[m]; Zsrc = Z_i; n = N_I; }
            else         { idx = sj[m - M_I]; Zsrc = Z_j; n = N_J; }
            float gt = Gate[idx * KDIM + lane];  // issue early
            float zv = Zsrc[lane * n + idx];
            float mx = zv;
#pragma unroll
            for (int o = 16; o; o >>= 1) mx = fmaxf(mx, __shfl_xor_sync(0xffffffffu, mx, o));
            float e = __expf(zv - mx);
            float es = e;
#pragma unroll
            for (int o = 16; o; o >>= 1) es += __shfl_xor_sync(0xffffffffu, es, o);
            float z = e / es;

            float g = 1.f / (1.f + __expf(-gt));   // faithful: j-side indexes Gate w/o offset
            float w = z * g;
            sacc += w;
#pragma unroll
            for (int a = 0; a < KDIM; a++) {
                float za = __shfl_sync(0xffffffffu, z, a);
                tacc[a] = fmaf(za, w, tacc[a]);
            }
        }

        atomicAdd(&s_ss[lane], sacc);
#pragma unroll
        for (int a = 0; a < KDIM; a++) atomicAdd(&s_sT[a][lane], tacc[a]);
        __syncthreads();

        for (int e = tid; e < KDIM * KDIM; e += TPB)
            atomicAdd(&g_T[e], s_sT[e >> 5][e & 31]);
        if (tid < KDIM) atomicAdd(&g_s[tid], s_ss[tid]);
    }
    grid_bar(0);

    // ===== Phase 2: AZC (per block, redundant) + per-node latent rows =====
    {
        float (*az)[KDIM + 1] = s_sT;   // reuse; stride irrelevant for correctness
        for (int e = tid; e < DDIM * KDIM; e += TPB) {
            int dd = e >> 5, b = e & 31;
            float acc = 0.f;
#pragma unroll
            for (int a = 0; a < KDIM; a++) acc = fmaf(A[dd * KDIM + a], g_T[a * KDIM + b], acc);
            az[dd][b] = acc / g_s[b];
        }
        __syncthreads();

        for (int c = bid * TPB + tid; c < N_I + N_J; c += KA_GRID * TPB) {
            const float* Zsrc; float* X; float* q; int n, cc, side;
            if (c < N_I) { Zsrc = Z_i; X = g_Xi; q = g_qi; n = N_I; cc = c; side = 0; }
            else         { Zsrc = Z_j; X = g_Xj; q = g_qj; n = N_J; cc = c - N_I; side = 1; }

            float v[KDIM];
            float mx = -1e30f;
#pragma unroll
            for (int a = 0; a < KDIM; a++) { v[a] = Zsrc[a * n + cc]; mx = fmaxf(mx, v[a]); }
            float sum = 0.f;
#pragma unroll
            for (int a = 0; a < KDIM; a++) { v[a] = __expf(v[a] - mx); sum += v[a]; }
            float inv = 1.f / sum;

            float x[DDIM];
#pragma unroll
            for (int dd = 0; dd < DDIM; dd++) x[dd] = 0.f;
#pragma unroll
            for (int a = 0; a < KDIM; a++) {
                float z = v[a] * inv;
#pragma unroll
                for (int dd = 0; dd < DDIM; dd++) x[dd] = fmaf(az[dd][a], z, x[dd]);
            }
            float s2 = 0.f, s1 = 0.f;
            float4* o4 = (float4*)&X[cc * DDIM];
#pragma unroll
            for (int w = 0; w < DDIM / 4; w++) {
                float4 v4 = make_float4(x[4 * w], x[4 * w + 1], x[4 * w + 2], x[4 * w + 3]);
                s2 = fmaf(v4.x, v4.x, fmaf(v4.y, v4.y, fmaf(v4.z, v4.z, fmaf(v4.w, v4.w, s2))));
                s1 += v4.x + v4.y + v4.z + v4.w;
                o4[w] = v4;
            }
            q[cc] = side == 0 ? (s2 + 2.f * EPSV * s1) : (s2 - 2.f * EPSV * s1);
        }
    }
}

// ---------------- KB: pair tiles + edge chunks (item loop) --------------------
__global__ void __launch_bounds__(TPB, 2) kB_pair_edges(
    const float* __restrict__ beta, const float* __restrict__ gamma,
    const int* __restrict__ si, const int* __restrict__ sj,
    const int* __restrict__ spi, const int* __restrict__ spj,
    float* __restrict__ out)
{
    __shared__ float s_As[KDIM][BT + 4];   // 528B row base stays 16B aligned
    __shared__ float s_Bs[KDIM][BT + 4];
    __shared__ float s_qa[BT], s_ba[BT], s_qb[BT], s_gb[BT];
    __shared__ float s_red[TPB / 32];

    const int tid = threadIdx.x;

    for (int item = blockIdx.x; item < NITEMS; item += KB_GRID) {
        __syncthreads();   // protect smem reuse across item iterations
        if (item < NPAIR) {
            // ---- dense pairwise exp-distance tile (BT x BT) ----
            int ti = item / NTJ, tj = item - ti * NTJ;
            int i0 = ti * BT, j0 = tj * BT;

            // float4 gathers + conflict-free STS: lanes sweep rows, chunks sweep k
            for (int e = tid; e < BT * (DDIM / 4); e += TPB) {
                int chunk = e >> 7;            // 0..7: which float4 within the row
                int r = e & (BT - 1);          // tile row; lanes -> consecutive r
                float4 va = make_float4(0.f, 0.f, 0.f, 0.f);
                float4 vb = make_float4(0.f, 0.f, 0.f, 0.f);
                int rg = i0 + r;
                if (rg < M_I) va = *(const float4*)&g_Xi[si[rg] * DDIM + chunk * 4];
                rg = j0 + r;
                if (rg < M_J) vb = *(const float4*)&g_Xj[sj[rg] * DDIM + chunk * 4];
                int k4 = chunk * 4;
                s_As[k4 + 0][r] = va.x; s_As[k4 + 1][r] = va.y;
                s_As[k4 + 2][r] = va.z; s_As[k4 + 3][r] = va.w;
                s_Bs[k4 + 0][r] = vb.x; s_Bs[k4 + 1][r] = vb.y;
                s_Bs[k4 + 2][r] = vb.z; s_Bs[k4 + 3][r] = vb.w;
            }
            if (tid < BT) {
                int rg = i0 + tid;
                if (rg < M_I) { int idx = si[rg]; s_qa[tid] = g_qi[idx]; s_ba[tid] = beta[idx]; }
                else          { s_qa[tid] = 1e30f; s_ba[tid] = 0.f; }
            } else {
                int p = tid - BT;
                int rg = j0 + p;
                if (rg < M_J) { int idx = sj[rg]; s_qb[p] = g_qj[idx]; s_gb[p] = gamma[idx]; }
                else          { s_qb[p] = 1e30f; s_gb[p] = 0.f; }
            }
            __syncthreads();

            const int tx = tid & 15, ty = tid >> 4;
            const int r0 = ty * 8, c0 = tx * 8;

            unsigned long long acc[8][4];
#pragma unroll
            for (int r = 0; r < 8; r++)
#pragma unroll
                for (int c = 0; c < 4; c++) acc[r][c] = 0ULL;

#pragma unroll
            for (int kk = 0; kk < KDIM; kk++) {
                float4 a0 = *(const float4*)&s_As[kk][r0];
                float4 a1 = *(const float4*)&s_As[kk][r0 + 4];
                ulonglong2 b0 = *(const ulonglong2*)&s_Bs[kk][c0];
                ulonglong2 b1 = *(const ulonglong2*)&s_Bs[kk][c0 + 4];
                float av[8] = {a0.x, a0.y, a0.z, a0.w, a1.x, a1.y, a1.z, a1.w};
                unsigned long long bp[4] = {b0.x, b0.y, b1.x, b1.y};
#pragma unroll
                for (int r = 0; r < 8; r++) {
                    unsigned long long ad;
                    asm("mov.b64 %0, {%1, %1};" : "=l"(ad) : "f"(av[r]));
#pragma unroll
                    for (int c = 0; c < 4; c++) {
                        asm("fma.rn.f32x2 %0, %1, %2, %0;"
                            : "+l"(acc[r][c]) : "l"(ad), "l"(bp[c]));
                    }
                }
            }

            float sum = 0.f;
#pragma unroll
            for (int r = 0; r < 8; r++) {
                float qa = s_qa[r0 + r];
                float ba = s_ba[r0 + r];
#pragma unroll
                for (int c = 0; c < 4; c++) {
                    float dlo, dhi;
                    asm("mov.b64 {%0, %1}, %2;" : "=f"(dlo), "=f"(dhi) : "l"(acc[r][c]));
                    int cl = c0 + 2 * c;
                    float d2a = qa + s_qb[cl] - 2.f * dlo + C0;
                    float d2b = qa + s_qb[cl + 1] - 2.f * dhi + C0;
                    d2a = fmaxf(d2a, 0.f);
                    d2b = fmaxf(d2b, 0.f);
                    sum += __expf(ba + s_gb[cl] - fsqrt_fast(d2a));
                    sum += __expf(ba + s_gb[cl + 1] - fsqrt_fast(d2b));
                }
            }
            float bs = block_reduce(sum, s_red);
            if (tid == 0) atomicAdd(&g_mat, (double)bs);
        } else {
            // ---- sparse edge chunk ----
            int base = (item - NPAIR) * EDGE_PER_BLK;
            float sum = 0.f;
#pragma unroll
            for (int l = 0; l < EDGE_PER_BLK / TPB; l++) {
                int e = base + l * TPB + tid;
                if (e < N_EDGES) {
                    int ii = spi[e];
                    int jj = spj[e];
                    const float4* xa = (const float4*)&g_Xi[ii * DDIM];
                    const float4* xb = (const float4*)&g_Xj[jj * DDIM];
                    float dot = 0.f;
#pragma unroll
                    for (int w = 0; w < DDIM / 4; w++) {
                        float4 a = xa[w], b = xb[w];
                        dot = fmaf(a.x, b.x, dot);
                        dot = fmaf(a.y, b.y, dot);
                        dot = fmaf(a.z, b.z, dot);
                        dot = fmaf(a.w, b.w, dot);
                    }
                    float d2 = g_qi[ii] + g_qj[jj] - 2.f * dot + C0;
                    d2 = fmaxf(d2, 0.f);
                    sum += beta[ii] + gamma[jj] - fsqrt_fast(d2);
                }
            }
            float bs = block_reduce(sum, s_red);
            if (tid == 0) atomicAdd(&g_links, (double)bs);
        }
    }

    // ---- last-block-done: final scalar + reset ALL state for next replay ----
    __syncthreads();
    __threadfence();
    __shared__ unsigned int s_last;
    if (tid == 0) s_last = atomicAdd(&g_done, 1u);
    __syncthreads();
    if (s_last == KB_GRID - 1) {
        if (tid == 0) {
            double m = atomicAdd(&g_mat, 0.0);      // read after fence chain
            double l = atomicAdd(&g_links, 0.0);
            out[0] = (float)(l - m);
            g_mat = 0.0;
            g_links = 0.0;
            g_done = 0u;
            g_s[0] = 0.f;
            g_bar[0] = 0; g_bar[1] = 0;
        }
        for (int e = tid; e < KDIM * KDIM; e += TPB) g_T[e] = 0.f;
        if (tid > 0 && tid < KDIM) g_s[tid] = 0.f;
    }
}

// ---------------- launcher -----------------------------------------------------
extern "C" void kernel_launch(void* const* d_in, const int* in_sizes, int n_in,
                              void* d_out, int out_size) {
    const float* beta  = (const float*)d_in[0];
    const float* gamma = (const float*)d_in[1];
    const float* A     = (const float*)d_in[2];
    const float* Z_i   = (const float*)d_in[3];
    const float* Z_j   = (const float*)d_in[4];
    const float* Gate  = (const float*)d_in[5];
    const int* si      = (const int*)d_in[6];
    const int* sj      = (const int*)d_in[7];
    const int* spi     = (const int*)d_in[8];
    const int* spj     = (const int*)d_in[9];
    float* out = (float*)d_out;

    kA_stats_latent<<<KA_GRID, TPB>>>(A, Z_i, Z_j, Gate, si, sj);
    kB_pair_edges<<<KB_GRID, TPB>>>(beta, gamma, si, sj, spi, spj, out);
}